// round 15
// baseline (speedup 1.0000x reference)
#include <cuda_runtime.h>
#include <cuda_bf16.h>
#include <cuda_fp8.h>
#include <cstdint>
#include <math.h>

#define UU 4096   // rows (K of the Gram)
#define PP 1024   // feature dim (M=N of the Gram)
#define NTILE 8   // 1024/128 tiles per Gram dim
#define NPAIR 36  // upper-triangle tile pairs
#define KC 128    // K (fp8) per pipeline chunk
#define KQ 1024   // K per quarter
#define NCHUNK (KQ / KC)           // 8
#define SUB_BYTES 16384            // 128 rows x 128 fp8 = 128B/row
#define STAGE_BYTES (2 * SUB_BYTES) // A + B = 32KB
#define NST 3
#define GRAM_SMEM (NST * STAGE_BYTES + 128)   // ~96KB -> 2 CTAs/SM
#define GS_WORDS (2 * NPAIR * 8192)           // summed bf16x2 tiles

// ---- scratch (device globals; zero-initialized at load) ----
__device__ uint8_t g_b1T[PP * UU];        // normalized input1 (e4m3), transposed [c][k]
__device__ uint8_t g_b2T[PP * UU];        // normalized input2 (e4m3), transposed [c][k]
__device__ float g_inv[2 * UU];           // per-row 1/max(norm,eps)
__device__ float g_S[2 * PP];             // column sums (fp32, atomic accumulated)
__device__ uint32_t g_GS[GS_WORDS];       // SUMMED bf16x2 Gram tiles [g][pair][128*64]
__device__ float g_part[NPAIR];           // per-pair cross partials
__device__ unsigned g_done;

// ============================ helpers =======================================
__device__ __forceinline__ uint32_t smem_u32(const void* p) {
    uint32_t a;
    asm("{ .reg .u64 t; cvta.to.shared.u64 t, %1; cvt.u32.u64 %0, t; }" : "=r"(a) : "l"(p));
    return a;
}
__device__ __forceinline__ void cp_async16(uint32_t sdst, const void* gsrc) {
    asm volatile("cp.async.cg.shared.global [%0], [%1], 16;" :: "r"(sdst), "l"(gsrc) : "memory");
}
__device__ __forceinline__ void cp_commit() {
    asm volatile("cp.async.commit_group;" ::: "memory");
}
__device__ __forceinline__ void ldsm_x4(uint32_t& r0, uint32_t& r1, uint32_t& r2, uint32_t& r3,
                                        uint32_t addr) {
    asm volatile("ldmatrix.sync.aligned.m8n8.x4.shared.b16 {%0, %1, %2, %3}, [%4];"
                 : "=r"(r0), "=r"(r1), "=r"(r2), "=r"(r3) : "r"(addr));
}
__device__ __forceinline__ void mma16832(float* c, uint32_t a0, uint32_t a1, uint32_t a2,
                                         uint32_t a3, uint32_t b0, uint32_t b1) {
    asm volatile(
        "mma.sync.aligned.m16n8k32.row.col.f32.e4m3.e4m3.f32 "
        "{%0, %1, %2, %3}, {%4, %5, %6, %7}, {%8, %9}, {%0, %1, %2, %3};"
        : "+f"(c[0]), "+f"(c[1]), "+f"(c[2]), "+f"(c[3])
        : "r"(a0), "r"(a1), "r"(a2), "r"(a3), "r"(b0), "r"(b1));
}
__device__ __forceinline__ uint32_t fp8x4(float a, float b, float c, float d) {
    __nv_fp8x2_storage_t lo = __nv_cvt_float2_to_fp8x2(make_float2(a, b),
                                                       __NV_SATFINITE, __NV_E4M3);
    __nv_fp8x2_storage_t hi = __nv_cvt_float2_to_fp8x2(make_float2(c, d),
                                                       __NV_SATFINITE, __NV_E4M3);
    return (uint32_t)lo | ((uint32_t)hi << 16);
}

// ============================ kernels =======================================

// per-row inverse norms (warp per row) + zero the summed-G accumulator tiles
__global__ void __launch_bounds__(256) norm_k(const float* __restrict__ in1,
                                              const float* __restrict__ in2) {
    // zero g_GS: 147456 uint4 across 262144 threads
    int zt = blockIdx.x * 256 + threadIdx.x;
    if (zt < GS_WORDS / 4)
        ((uint4*)g_GS)[zt] = make_uint4(0u, 0u, 0u, 0u);

    int row_g = blockIdx.x * 8 + (threadIdx.x >> 5);   // 0..8191
    int lane = threadIdx.x & 31;
    const float* src = (row_g < UU) ? in1 : in2;
    int row = row_g & (UU - 1);
    const float4* p = (const float4*)(src + (size_t)row * PP) + lane;

    float4 v0 = p[0],   v1 = p[32],  v2 = p[64],  v3 = p[96];
    float4 v4 = p[128], v5 = p[160], v6 = p[192], v7 = p[224];
    float s0 = v0.x * v0.x + v0.y * v0.y + v0.z * v0.z + v0.w * v0.w
             + v1.x * v1.x + v1.y * v1.y + v1.z * v1.z + v1.w * v1.w;
    float s1 = v2.x * v2.x + v2.y * v2.y + v2.z * v2.z + v2.w * v2.w
             + v3.x * v3.x + v3.y * v3.y + v3.z * v3.z + v3.w * v3.w;
    float s2 = v4.x * v4.x + v4.y * v4.y + v4.z * v4.z + v4.w * v4.w
             + v5.x * v5.x + v5.y * v5.y + v5.z * v5.z + v5.w * v5.w;
    float s3 = v6.x * v6.x + v6.y * v6.y + v6.z * v6.z + v6.w * v6.w
             + v7.x * v7.x + v7.y * v7.y + v7.z * v7.z + v7.w * v7.w;
    float ss = (s0 + s1) + (s2 + s3);
    #pragma unroll
    for (int o = 16; o > 0; o >>= 1) ss += __shfl_xor_sync(0xffffffffu, ss, o);
    if (lane == 0)
        g_inv[row_g] = 1.0f / fmaxf(sqrtf(ss), 1e-8f);
}

// fused scale + e4m3 convert + transpose (64x64 tiles) + partial column sums
__global__ void __launch_bounds__(256) conv_k(const float* __restrict__ in1,
                                              const float* __restrict__ in2) {
    int mat = blockIdx.z;
    const float* src = mat ? in2 : in1;
    uint8_t* dst = mat ? g_b2T : g_b1T;
    int c0 = blockIdx.x * 64, k0 = blockIdx.y * 64;
    __shared__ float s[64][65];
    int tid = threadIdx.x;
    #pragma unroll
    for (int r = 0; r < 4; r++) {
        int li = r * 256 + tid;
        int k = li >> 4, c4 = (li & 15) << 2;
        float4 v = *(const float4*)&src[(size_t)(k0 + k) * PP + c0 + c4];
        float inv = g_inv[mat * UU + k0 + k];
        s[c4 + 0][k] = v.x * inv; s[c4 + 1][k] = v.y * inv;
        s[c4 + 2][k] = v.z * inv; s[c4 + 3][k] = v.w * inv;
    }
    __syncthreads();
    int c = tid >> 2, kg = (tid & 3) << 4;
    uint32_t pk[4];
    #pragma unroll
    for (int t = 0; t < 4; t++)
        pk[t] = fp8x4(s[c][kg + 4 * t], s[c][kg + 4 * t + 1],
                      s[c][kg + 4 * t + 2], s[c][kg + 4 * t + 3]);
    *(uint4*)&dst[(size_t)(c0 + c) * UU + k0 + kg] = make_uint4(pk[0], pk[1], pk[2], pk[3]);
    float cs = 0.f;
    #pragma unroll
    for (int i = 0; i < 16; i++) cs += s[c][kg + i];
    cs += __shfl_xor_sync(0xffffffffu, cs, 1);
    cs += __shfl_xor_sync(0xffffffffu, cs, 2);
    if ((tid & 3) == 0) atomicAdd(&g_S[mat * PP + c0 + c], cs);
}

// FP8 Gram: grid 288 = 2 grams x 36 pairs x 4 K-quarters.
// 128 threads / 4 warps, 64x64 warp tiles (2x2); 96KB smem -> 2 CTAs/SM.
// Epilogue: atomicAdd bf16x2 into the SUMMED tile g_GS (quarters accumulate).
__global__ void __launch_bounds__(128, 2) gram_k() {
    extern __shared__ char dyn[];
    int b = blockIdx.x;
    int g = (b >= 144); int r0_ = b - g * 144;
    int q = r0_ / NPAIR; int pair = r0_ - q * NPAIR;
    int pt = 0, rem = pair;
    while (rem >= NTILE - pt) { rem -= NTILE - pt; pt++; }
    int qt = pt + rem;

    const uint8_t* src = g ? g_b2T : g_b1T;
    const uint4* PA = (const uint4*)src + (size_t)(pt * 128) * 256 + q * 64;
    const uint4* PB = (const uint4*)src + (size_t)(qt * 128) * 256 + q * 64;

    int tid = threadIdx.x;
    uint32_t sbase = (smem_u32(dyn) + 127u) & ~127u;

    int m0 = tid >> 3, c = tid & 7;
    int gbase = m0 * 256 + c;
    uint32_t sob = (uint32_t)(m0 * 128 + ((c ^ (m0 & 7)) << 4));

    int wid = tid >> 5, lane = tid & 31;
    int wm = wid >> 1, wn = wid & 1;
    int m_base = wm * 64, n_base = wn * 64;
    int lrow = lane & 15, lcol = lane >> 4;
    uint32_t offA[4], swA[4], offB[4], swB[4];
    #pragma unroll
    for (int t = 0; t < 4; t++) {
        int rwa = m_base + t * 16 + lrow;
        offA[t] = (uint32_t)(rwa * 128); swA[t] = (uint32_t)(rwa & 7);
        int rwb = n_base + t * 16 + lrow;
        offB[t] = (uint32_t)(rwb * 128); swB[t] = (uint32_t)(rwb & 7);
    }

    float acc[4][8][4];
    #pragma unroll
    for (int i = 0; i < 4; i++)
        #pragma unroll
        for (int j = 0; j < 8; j++)
            #pragma unroll
            for (int k = 0; k < 4; k++) acc[i][j][k] = 0.f;

    #pragma unroll
    for (int st = 0; st < 2; st++) {
        uint32_t sA = sbase + (uint32_t)(st * STAGE_BYTES);
        uint32_t sB = sA + SUB_BYTES;
        int k4 = st * 8;
        #pragma unroll
        for (int r = 0; r < 8; r++) {
            cp_async16(sA + sob + r * 2048, PA + gbase + r * 4096 + k4);
            cp_async16(sB + sob + r * 2048, PB + gbase + r * 4096 + k4);
        }
        cp_commit();
    }

    for (int ch = 0; ch < NCHUNK; ch++) {
        if (ch < NCHUNK - 1) asm volatile("cp.async.wait_group 1;" ::: "memory");
        else                 asm volatile("cp.async.wait_group 0;" ::: "memory");
        __syncthreads();
        if (ch + 2 < NCHUNK) {
            int st = (ch + 2) % NST;
            uint32_t sA = sbase + (uint32_t)(st * STAGE_BYTES);
            uint32_t sB = sA + SUB_BYTES;
            int k4 = (ch + 2) * 8;
            #pragma unroll
            for (int r = 0; r < 8; r++) {
                cp_async16(sA + sob + r * 2048, PA + gbase + r * 4096 + k4);
                cp_async16(sB + sob + r * 2048, PB + gbase + r * 4096 + k4);
            }
            cp_commit();
        }
        uint32_t sA = sbase + (uint32_t)((ch % NST) * STAGE_BYTES);
        uint32_t sB = sA + SUB_BYTES;
        #pragma unroll
        for (int kk = 0; kk < 4; kk++) {
            uint32_t cbase = (uint32_t)(kk * 2 + lcol);
            uint32_t bf[4][4];
            #pragma unroll
            for (int nt2 = 0; nt2 < 4; nt2++)
                ldsm_x4(bf[nt2][0], bf[nt2][1], bf[nt2][2], bf[nt2][3],
                        sB + offB[nt2] + (((cbase ^ swB[nt2]) & 7u) << 4));
            #pragma unroll
            for (int mt = 0; mt < 4; mt++) {
                uint32_t a0, a1, a2, a3;
                ldsm_x4(a0, a1, a2, a3,
                        sA + offA[mt] + (((cbase ^ swA[mt]) & 7u) << 4));
                #pragma unroll
                for (int nt2 = 0; nt2 < 4; nt2++) {
                    mma16832(acc[mt][2 * nt2 + 0], a0, a1, a2, a3, bf[nt2][0], bf[nt2][2]);
                    mma16832(acc[mt][2 * nt2 + 1], a0, a1, a2, a3, bf[nt2][1], bf[nt2][3]);
                }
            }
        }
    }

    // epilogue: atomic-accumulate bf16x2 into the summed per-(g,pair) tile
    int er = lane >> 2, ec = (lane & 3) << 1;
    __nv_bfloat162* out = (__nv_bfloat162*)(g_GS + (size_t)(g * NPAIR + pair) * 8192);
    #pragma unroll
    for (int mt = 0; mt < 4; mt++)
        #pragma unroll
        for (int nt = 0; nt < 8; nt++) {
            int row = m_base + mt * 16 + er;
            int col = n_base + nt * 8 + ec;
            __nv_bfloat162 q0 = __floats2bfloat162_rn(acc[mt][nt][0], acc[mt][nt][1]);
            __nv_bfloat162 q1 = __floats2bfloat162_rn(acc[mt][nt][2], acc[mt][nt][3]);
            atomicAdd(&out[(row * 128 + col) >> 1], q0);
            atomicAdd(&out[((row + 8) * 128 + col) >> 1], q1);
        }
}

// cross-dot on SUMMED bf16 tiles + last-block finalize (+ reset for replay)
__global__ void __launch_bounds__(256) dot_k(float* __restrict__ out) {
    int pair = blockIdx.x >> 3;
    int part = blockIdx.x & 7;
    int pt = 0, rem = pair;
    while (rem >= NTILE - pt) { rem -= NTILE - pt; pt++; }
    float w = (rem == 0) ? 1.0f : 2.0f;

    int tid = threadIdx.x;
    int idx = part * 256 + tid;   // uint4 index within tile (2048 total)
    uint4 xa = ((const uint4*)(g_GS + (size_t)pair * 8192))[idx];
    uint4 ya = ((const uint4*)(g_GS + (size_t)(NPAIR + pair) * 8192))[idx];

    float s = 0.f;
    uint32_t wa[4] = {xa.x, xa.y, xa.z, xa.w};
    uint32_t wc[4] = {ya.x, ya.y, ya.z, ya.w};
    #pragma unroll
    for (int i = 0; i < 4; i++) {
        float2 fa = __bfloat1622float2(*(__nv_bfloat162*)&wa[i]);
        float2 fc = __bfloat1622float2(*(__nv_bfloat162*)&wc[i]);
        s += fa.x * fc.x + fa.y * fc.y;
    }
    #pragma unroll
    for (int o = 16; o > 0; o >>= 1) s += __shfl_xor_sync(0xffffffffu, s, o);
    __shared__ float ws[8];
    if ((tid & 31) == 0) ws[tid >> 5] = s;
    __syncthreads();
    __shared__ int is_last;
    if (tid == 0) {
        float t = ws[0] + ws[1] + ws[2] + ws[3] + ws[4] + ws[5] + ws[6] + ws[7];
        atomicAdd(&g_part[pair], w * t);
        __threadfence();
        is_last = (atomicAdd(&g_done, 1u) == (unsigned)(gridDim.x - 1));
        if (is_last) __threadfence();
    }
    __syncthreads();
    if (is_last) {
        float sd = 0.f;
        #pragma unroll
        for (int r = 0; r < 4; r++) {
            int c = tid + r * 256;
            sd += g_S[c] * g_S[PP + c];
        }
        float cp = (tid < NPAIR) ? g_part[tid] : 0.0f;
        #pragma unroll
        for (int o = 16; o > 0; o >>= 1) {
            sd += __shfl_xor_sync(0xffffffffu, sd, o);
            cp += __shfl_xor_sync(0xffffffffu, cp, o);
        }
        __shared__ float wc2[8];
        if ((tid & 31) == 0) { ws[tid >> 5] = sd; wc2[tid >> 5] = cp; }
        __syncthreads();
        if (tid == 0) {
            float dot = ws[0] + ws[1] + ws[2] + ws[3] + ws[4] + ws[5] + ws[6] + ws[7];
            float cr  = wc2[0] + wc2[1] + wc2[2] + wc2[3] + wc2[4] + wc2[5] + wc2[6] + wc2[7];
            out[0] = (float)(16777216.0 - 2.0 * (double)dot + (double)cr);
        }
        __syncthreads();
        #pragma unroll
        for (int r = 0; r < 8; r++) g_S[tid + r * 256] = 0.0f;
        if (tid < NPAIR) g_part[tid] = 0.0f;
        if (tid == 0) g_done = 0u;
    }
}

// ============================================================================
extern "C" void kernel_launch(void* const* d_in, const int* in_sizes, int n_in,
                              void* d_out, int out_size) {
    const float* in1 = (const float*)d_in[0];
    const float* in2 = (const float*)d_in[1];
    float* out = (float*)d_out;

    cudaFuncSetAttribute(gram_k, cudaFuncAttributeMaxDynamicSharedMemorySize, GRAM_SMEM);

    norm_k<<<1024, 256>>>(in1, in2);
    conv_k<<<dim3(PP / 64, UU / 64, 2), 256>>>(in1, in2);
    gram_k<<<288, 128, GRAM_SMEM>>>();
    dot_k<<<NPAIR * 8, 256>>>(out);
}

// round 16
// speedup vs baseline: 1.0064x; 1.0064x over previous
#include <cuda_runtime.h>
#include <cuda_bf16.h>
#include <cuda_fp8.h>
#include <cstdint>
#include <math.h>

#define UU 4096   // rows (K of the Gram)
#define PP 1024   // feature dim (M=N of the Gram)
#define NTILE 8   // 1024/128 tiles per Gram dim
#define NPAIR 36  // upper-triangle tile pairs
#define KC 128    // K (fp8) per pipeline chunk
#define KQ 1024   // K per quarter
#define NCHUNK (KQ / KC)           // 8
#define SUB_BYTES 16384            // 128 rows x 128 fp8 = 128B/row
#define STAGE_BYTES (2 * SUB_BYTES) // A + B = 32KB
#define NST 3
#define GRAM_SMEM (NST * STAGE_BYTES + 128)   // ~96KB -> 2 CTAs/SM

// ---- scratch (device globals; zero-initialized at load) ----
__device__ uint8_t g_b1T[PP * UU];        // normalized input1 (e4m3), transposed [c][k]
__device__ uint8_t g_b2T[PP * UU];        // normalized input2 (e4m3), transposed [c][k]
__device__ float g_inv[2 * UU];           // per-row 1/max(norm,eps)
__device__ float g_S[2 * PP];             // column sums (fp32, atomic accumulated)
__device__ uint32_t g_Gb[8 * NPAIR * 8192]; // bf16x2 tiles [g*4+q][pair][128*64]
__device__ float g_part[NPAIR];           // per-pair cross partials
__device__ unsigned g_done;

// ============================ helpers =======================================
__device__ __forceinline__ uint32_t smem_u32(const void* p) {
    uint32_t a;
    asm("{ .reg .u64 t; cvta.to.shared.u64 t, %1; cvt.u32.u64 %0, t; }" : "=r"(a) : "l"(p));
    return a;
}
__device__ __forceinline__ void cp_async16(uint32_t sdst, const void* gsrc) {
    asm volatile("cp.async.cg.shared.global [%0], [%1], 16;" :: "r"(sdst), "l"(gsrc) : "memory");
}
__device__ __forceinline__ void cp_commit() {
    asm volatile("cp.async.commit_group;" ::: "memory");
}
__device__ __forceinline__ void ldsm_x4(uint32_t& r0, uint32_t& r1, uint32_t& r2, uint32_t& r3,
                                        uint32_t addr) {
    asm volatile("ldmatrix.sync.aligned.m8n8.x4.shared.b16 {%0, %1, %2, %3}, [%4];"
                 : "=r"(r0), "=r"(r1), "=r"(r2), "=r"(r3) : "r"(addr));
}
__device__ __forceinline__ void mma16832(float* c, uint32_t a0, uint32_t a1, uint32_t a2,
                                         uint32_t a3, uint32_t b0, uint32_t b1) {
    asm volatile(
        "mma.sync.aligned.m16n8k32.row.col.f32.e4m3.e4m3.f32 "
        "{%0, %1, %2, %3}, {%4, %5, %6, %7}, {%8, %9}, {%0, %1, %2, %3};"
        : "+f"(c[0]), "+f"(c[1]), "+f"(c[2]), "+f"(c[3])
        : "r"(a0), "r"(a1), "r"(a2), "r"(a3), "r"(b0), "r"(b1));
}
__device__ __forceinline__ uint32_t fp8x4(float a, float b, float c, float d) {
    __nv_fp8x2_storage_t lo = __nv_cvt_float2_to_fp8x2(make_float2(a, b),
                                                       __NV_SATFINITE, __NV_E4M3);
    __nv_fp8x2_storage_t hi = __nv_cvt_float2_to_fp8x2(make_float2(c, d),
                                                       __NV_SATFINITE, __NV_E4M3);
    return (uint32_t)lo | ((uint32_t)hi << 16);
}

// ============================ kernels =======================================

// per-row inverse norms: one WARP per row (grid 1024, 8 rows/CTA)
__global__ void __launch_bounds__(256) norm_k(const float* __restrict__ in1,
                                              const float* __restrict__ in2) {
    int row_g = blockIdx.x * 8 + (threadIdx.x >> 5);   // 0..8191
    int lane = threadIdx.x & 31;
    const float* src = (row_g < UU) ? in1 : in2;
    int row = row_g & (UU - 1);
    const float4* p = (const float4*)(src + (size_t)row * PP) + lane;

    float4 v0 = p[0],   v1 = p[32],  v2 = p[64],  v3 = p[96];
    float4 v4 = p[128], v5 = p[160], v6 = p[192], v7 = p[224];
    float s0 = v0.x * v0.x + v0.y * v0.y + v0.z * v0.z + v0.w * v0.w
             + v1.x * v1.x + v1.y * v1.y + v1.z * v1.z + v1.w * v1.w;
    float s1 = v2.x * v2.x + v2.y * v2.y + v2.z * v2.z + v2.w * v2.w
             + v3.x * v3.x + v3.y * v3.y + v3.z * v3.z + v3.w * v3.w;
    float s2 = v4.x * v4.x + v4.y * v4.y + v4.z * v4.z + v4.w * v4.w
             + v5.x * v5.x + v5.y * v5.y + v5.z * v5.z + v5.w * v5.w;
    float s3 = v6.x * v6.x + v6.y * v6.y + v6.z * v6.z + v6.w * v6.w
             + v7.x * v7.x + v7.y * v7.y + v7.z * v7.z + v7.w * v7.w;
    float ss = (s0 + s1) + (s2 + s3);
    #pragma unroll
    for (int o = 16; o > 0; o >>= 1) ss += __shfl_xor_sync(0xffffffffu, ss, o);
    if (lane == 0)
        g_inv[row_g] = 1.0f / fmaxf(sqrtf(ss), 1e-8f);
}

// fused scale + e4m3 convert + transpose (64x64 tiles) + partial column sums
__global__ void __launch_bounds__(256) conv_k(const float* __restrict__ in1,
                                              const float* __restrict__ in2) {
    int mat = blockIdx.z;
    const float* src = mat ? in2 : in1;
    uint8_t* dst = mat ? g_b2T : g_b1T;
    int c0 = blockIdx.x * 64, k0 = blockIdx.y * 64;
    __shared__ float s[64][65];
    int tid = threadIdx.x;
    #pragma unroll
    for (int r = 0; r < 4; r++) {
        int li = r * 256 + tid;
        int k = li >> 4, c4 = (li & 15) << 2;
        float4 v = *(const float4*)&src[(size_t)(k0 + k) * PP + c0 + c4];
        float inv = g_inv[mat * UU + k0 + k];
        s[c4 + 0][k] = v.x * inv; s[c4 + 1][k] = v.y * inv;
        s[c4 + 2][k] = v.z * inv; s[c4 + 3][k] = v.w * inv;
    }
    __syncthreads();
    int c = tid >> 2, kg = (tid & 3) << 4;
    uint32_t pk[4];
    #pragma unroll
    for (int t = 0; t < 4; t++)
        pk[t] = fp8x4(s[c][kg + 4 * t], s[c][kg + 4 * t + 1],
                      s[c][kg + 4 * t + 2], s[c][kg + 4 * t + 3]);
    *(uint4*)&dst[(size_t)(c0 + c) * UU + k0 + kg] = make_uint4(pk[0], pk[1], pk[2], pk[3]);
    float cs = 0.f;
    #pragma unroll
    for (int i = 0; i < 16; i++) cs += s[c][kg + i];
    cs += __shfl_xor_sync(0xffffffffu, cs, 1);
    cs += __shfl_xor_sync(0xffffffffu, cs, 2);
    if ((tid & 3) == 0) atomicAdd(&g_S[mat * PP + c0 + c], cs);
}

// FP8 Gram: grid 288 = 2 grams x 36 pairs x 4 K-quarters.
// 128 threads / 4 warps, 64x64 warp tiles (2x2); 96KB smem -> 2 CTAs/SM.
__global__ void __launch_bounds__(128, 2) gram_k() {
    extern __shared__ char dyn[];
    int b = blockIdx.x;
    int g = (b >= 144); int r0_ = b - g * 144;
    int q = r0_ / NPAIR; int pair = r0_ - q * NPAIR;
    int pt = 0, rem = pair;
    while (rem >= NTILE - pt) { rem -= NTILE - pt; pt++; }
    int qt = pt + rem;

    const uint8_t* src = g ? g_b2T : g_b1T;
    const uint4* PA = (const uint4*)src + (size_t)(pt * 128) * 256 + q * 64;
    const uint4* PB = (const uint4*)src + (size_t)(qt * 128) * 256 + q * 64;

    int tid = threadIdx.x;
    uint32_t sbase = (smem_u32(dyn) + 127u) & ~127u;

    int m0 = tid >> 3, c = tid & 7;
    int gbase = m0 * 256 + c;
    uint32_t sob = (uint32_t)(m0 * 128 + ((c ^ (m0 & 7)) << 4));

    int wid = tid >> 5, lane = tid & 31;
    int wm = wid >> 1, wn = wid & 1;
    int m_base = wm * 64, n_base = wn * 64;
    int lrow = lane & 15, lcol = lane >> 4;
    uint32_t offA[4], swA[4], offB[4], swB[4];
    #pragma unroll
    for (int t = 0; t < 4; t++) {
        int rwa = m_base + t * 16 + lrow;
        offA[t] = (uint32_t)(rwa * 128); swA[t] = (uint32_t)(rwa & 7);
        int rwb = n_base + t * 16 + lrow;
        offB[t] = (uint32_t)(rwb * 128); swB[t] = (uint32_t)(rwb & 7);
    }

    float acc[4][8][4];
    #pragma unroll
    for (int i = 0; i < 4; i++)
        #pragma unroll
        for (int j = 0; j < 8; j++)
            #pragma unroll
            for (int k = 0; k < 4; k++) acc[i][j][k] = 0.f;

    #pragma unroll
    for (int st = 0; st < 2; st++) {
        uint32_t sA = sbase + (uint32_t)(st * STAGE_BYTES);
        uint32_t sB = sA + SUB_BYTES;
        int k4 = st * 8;
        #pragma unroll
        for (int r = 0; r < 8; r++) {
            cp_async16(sA + sob + r * 2048, PA + gbase + r * 4096 + k4);
            cp_async16(sB + sob + r * 2048, PB + gbase + r * 4096 + k4);
        }
        cp_commit();
    }

    for (int ch = 0; ch < NCHUNK; ch++) {
        if (ch < NCHUNK - 1) asm volatile("cp.async.wait_group 1;" ::: "memory");
        else                 asm volatile("cp.async.wait_group 0;" ::: "memory");
        __syncthreads();
        if (ch + 2 < NCHUNK) {
            int st = (ch + 2) % NST;
            uint32_t sA = sbase + (uint32_t)(st * STAGE_BYTES);
            uint32_t sB = sA + SUB_BYTES;
            int k4 = (ch + 2) * 8;
            #pragma unroll
            for (int r = 0; r < 8; r++) {
                cp_async16(sA + sob + r * 2048, PA + gbase + r * 4096 + k4);
                cp_async16(sB + sob + r * 2048, PB + gbase + r * 4096 + k4);
            }
            cp_commit();
        }
        uint32_t sA = sbase + (uint32_t)((ch % NST) * STAGE_BYTES);
        uint32_t sB = sA + SUB_BYTES;
        #pragma unroll
        for (int kk = 0; kk < 4; kk++) {
            uint32_t cbase = (uint32_t)(kk * 2 + lcol);
            uint32_t bf[4][4];
            #pragma unroll
            for (int nt2 = 0; nt2 < 4; nt2++)
                ldsm_x4(bf[nt2][0], bf[nt2][1], bf[nt2][2], bf[nt2][3],
                        sB + offB[nt2] + (((cbase ^ swB[nt2]) & 7u) << 4));
            #pragma unroll
            for (int mt = 0; mt < 4; mt++) {
                uint32_t a0, a1, a2, a3;
                ldsm_x4(a0, a1, a2, a3,
                        sA + offA[mt] + (((cbase ^ swA[mt]) & 7u) << 4));
                #pragma unroll
                for (int nt2 = 0; nt2 < 4; nt2++) {
                    mma16832(acc[mt][2 * nt2 + 0], a0, a1, a2, a3, bf[nt2][0], bf[nt2][2]);
                    mma16832(acc[mt][2 * nt2 + 1], a0, a1, a2, a3, bf[nt2][1], bf[nt2][3]);
                }
            }
        }
    }

    // epilogue: direct per-warp bf16 pack
    int er = lane >> 2, ec = (lane & 3) << 1;
    uint32_t* out = g_Gb + (size_t)((g * 4 + q) * NPAIR + pair) * 8192;
    #pragma unroll
    for (int mt = 0; mt < 4; mt++)
        #pragma unroll
        for (int nt = 0; nt < 8; nt++) {
            int row = m_base + mt * 16 + er;
            int col = n_base + nt * 8 + ec;
            __nv_bfloat162 q0 = __floats2bfloat162_rn(acc[mt][nt][0], acc[mt][nt][1]);
            __nv_bfloat162 q1 = __floats2bfloat162_rn(acc[mt][nt][2], acc[mt][nt][3]);
            out[(row * 128 + col) >> 1]       = *(uint32_t*)&q0;
            out[((row + 8) * 128 + col) >> 1] = *(uint32_t*)&q1;
        }
}

// cross-dot: grid 144 (4 parts/pair); each thread batches 16 uint4 loads
// (2 idx positions x 8 tile sets) before converting; finalize + reset.
__global__ void __launch_bounds__(256) dot_k(float* __restrict__ out) {
    int pair = blockIdx.x >> 2;
    int part = blockIdx.x & 3;
    int pt = 0, rem = pair;
    while (rem >= NTILE - pt) { rem -= NTILE - pt; pt++; }
    float w = (rem == 0) ? 1.0f : 2.0f;

    int tid = threadIdx.x;
    int idx0 = part * 512 + tid;       // uint4 index (tile has 2048)
    int idx1 = idx0 + 256;

    // batch all 16 independent loads first (max MLP), then convert
    uint4 ra[4][2], rb[4][2];
    #pragma unroll
    for (int qq = 0; qq < 4; qq++) {
        const uint4* pa = (const uint4*)(g_Gb + (size_t)(qq * NPAIR + pair) * 8192);
        ra[qq][0] = pa[idx0]; ra[qq][1] = pa[idx1];
    }
    #pragma unroll
    for (int qq = 0; qq < 4; qq++) {
        const uint4* pb = (const uint4*)(g_Gb + (size_t)((4 + qq) * NPAIR + pair) * 8192);
        rb[qq][0] = pb[idx0]; rb[qq][1] = pb[idx1];
    }

    float s = 0.f;
    #pragma unroll
    for (int h = 0; h < 2; h++) {
        float g1[8], g2[8];
        #pragma unroll
        for (int i = 0; i < 8; i++) { g1[i] = 0.f; g2[i] = 0.f; }
        #pragma unroll
        for (int qq = 0; qq < 4; qq++) {
            uint32_t wa[4] = {ra[qq][h].x, ra[qq][h].y, ra[qq][h].z, ra[qq][h].w};
            uint32_t wc[4] = {rb[qq][h].x, rb[qq][h].y, rb[qq][h].z, rb[qq][h].w};
            #pragma unroll
            for (int i = 0; i < 4; i++) {
                float2 fa = __bfloat1622float2(*(__nv_bfloat162*)&wa[i]);
                float2 fc = __bfloat1622float2(*(__nv_bfloat162*)&wc[i]);
                g1[2 * i] += fa.x; g1[2 * i + 1] += fa.y;
                g2[2 * i] += fc.x; g2[2 * i + 1] += fc.y;
            }
        }
        #pragma unroll
        for (int i = 0; i < 8; i++) s += g1[i] * g2[i];
    }

    #pragma unroll
    for (int o = 16; o > 0; o >>= 1) s += __shfl_xor_sync(0xffffffffu, s, o);
    __shared__ float ws[8];
    if ((tid & 31) == 0) ws[tid >> 5] = s;
    __syncthreads();
    __shared__ int is_last;
    if (tid == 0) {
        float t = ws[0] + ws[1] + ws[2] + ws[3] + ws[4] + ws[5] + ws[6] + ws[7];
        atomicAdd(&g_part[pair], w * t);
        __threadfence();
        is_last = (atomicAdd(&g_done, 1u) == (unsigned)(gridDim.x - 1));
        if (is_last) __threadfence();
    }
    __syncthreads();
    if (is_last) {
        float sd = 0.f;
        #pragma unroll
        for (int r = 0; r < 4; r++) {
            int c = tid + r * 256;
            sd += g_S[c] * g_S[PP + c];
        }
        float cp = (tid < NPAIR) ? g_part[tid] : 0.0f;
        #pragma unroll
        for (int o = 16; o > 0; o >>= 1) {
            sd += __shfl_xor_sync(0xffffffffu, sd, o);
            cp += __shfl_xor_sync(0xffffffffu, cp, o);
        }
        __shared__ float wc2[8];
        if ((tid & 31) == 0) { ws[tid >> 5] = sd; wc2[tid >> 5] = cp; }
        __syncthreads();
        if (tid == 0) {
            float dot = ws[0] + ws[1] + ws[2] + ws[3] + ws[4] + ws[5] + ws[6] + ws[7];
            float cr  = wc2[0] + wc2[1] + wc2[2] + wc2[3] + wc2[4] + wc2[5] + wc2[6] + wc2[7];
            out[0] = (float)(16777216.0 - 2.0 * (double)dot + (double)cr);
        }
        __syncthreads();
        #pragma unroll
        for (int r = 0; r < 8; r++) g_S[tid + r * 256] = 0.0f;
        if (tid < NPAIR) g_part[tid] = 0.0f;
        if (tid == 0) g_done = 0u;
    }
}

// ============================================================================
extern "C" void kernel_launch(void* const* d_in, const int* in_sizes, int n_in,
                              void* d_out, int out_size) {
    const float* in1 = (const float*)d_in[0];
    const float* in2 = (const float*)d_in[1];
    float* out = (float*)d_out;

    cudaFuncSetAttribute(gram_k, cudaFuncAttributeMaxDynamicSharedMemorySize, GRAM_SMEM);

    norm_k<<<1024, 256>>>(in1, in2);
    conv_k<<<dim3(PP / 64, UU / 64, 2), 256>>>(in1, in2);
    gram_k<<<288, 128, GRAM_SMEM>>>();
    dot_k<<<NPAIR * 4, 256>>>(out);
}

// round 17
// speedup vs baseline: 1.0544x; 1.0477x over previous
#include <cuda_runtime.h>
#include <cuda_bf16.h>
#include <cuda_fp8.h>
#include <cstdint>
#include <math.h>

#define UU 4096   // rows (K of the Gram)
#define PP 1024   // feature dim (M=N of the Gram)
#define NTILE 8   // 1024/128 tiles per Gram dim
#define NPAIR 36  // upper-triangle tile pairs
#define KC 128    // K (fp8) per pipeline chunk
#define KQ 1024   // K per quarter
#define NCHUNK (KQ / KC)           // 8
#define SUB_BYTES 16384            // 128 rows x 128 fp8 = 128B/row
#define STAGE_BYTES (2 * SUB_BYTES) // A + B = 32KB
#define NST 3
#define GRAM_SMEM (NST * STAGE_BYTES + 128)   // ~96KB -> 2 CTAs/SM

// ---- scratch (device globals; zero-initialized at load) ----
__device__ uint8_t g_b1T[PP * UU];        // normalized input1 (e4m3), transposed [c][k]
__device__ uint8_t g_b2T[PP * UU];        // normalized input2 (e4m3), transposed [c][k]
__device__ float g_inv[2 * UU];           // per-row 1/max(norm,eps)
__device__ float g_S[2 * PP];             // column sums (fp32, atomic accumulated)
__device__ uint32_t g_Gb[8 * NPAIR * 8192]; // bf16x2 tiles [g*4+q][pair][128*64]
__device__ float g_part[NPAIR];           // per-pair cross partials
__device__ unsigned g_done;

// ============================ helpers =======================================
__device__ __forceinline__ uint32_t smem_u32(const void* p) {
    uint32_t a;
    asm("{ .reg .u64 t; cvta.to.shared.u64 t, %1; cvt.u32.u64 %0, t; }" : "=r"(a) : "l"(p));
    return a;
}
__device__ __forceinline__ void cp_async16(uint32_t sdst, const void* gsrc) {
    asm volatile("cp.async.cg.shared.global [%0], [%1], 16;" :: "r"(sdst), "l"(gsrc) : "memory");
}
__device__ __forceinline__ void cp_commit() {
    asm volatile("cp.async.commit_group;" ::: "memory");
}
__device__ __forceinline__ void ldsm_x4(uint32_t& r0, uint32_t& r1, uint32_t& r2, uint32_t& r3,
                                        uint32_t addr) {
    asm volatile("ldmatrix.sync.aligned.m8n8.x4.shared.b16 {%0, %1, %2, %3}, [%4];"
                 : "=r"(r0), "=r"(r1), "=r"(r2), "=r"(r3) : "r"(addr));
}
__device__ __forceinline__ void mma16832(float* c, uint32_t a0, uint32_t a1, uint32_t a2,
                                         uint32_t a3, uint32_t b0, uint32_t b1) {
    asm volatile(
        "mma.sync.aligned.m16n8k32.row.col.f32.e4m3.e4m3.f32 "
        "{%0, %1, %2, %3}, {%4, %5, %6, %7}, {%8, %9}, {%0, %1, %2, %3};"
        : "+f"(c[0]), "+f"(c[1]), "+f"(c[2]), "+f"(c[3])
        : "r"(a0), "r"(a1), "r"(a2), "r"(a3), "r"(b0), "r"(b1));
}
__device__ __forceinline__ uint32_t fp8x4(float a, float b, float c, float d) {
    __nv_fp8x2_storage_t lo = __nv_cvt_float2_to_fp8x2(make_float2(a, b),
                                                       __NV_SATFINITE, __NV_E4M3);
    __nv_fp8x2_storage_t hi = __nv_cvt_float2_to_fp8x2(make_float2(c, d),
                                                       __NV_SATFINITE, __NV_E4M3);
    return (uint32_t)lo | ((uint32_t)hi << 16);
}

// ============================ kernels =======================================

// per-row inverse norms: one WARP per row (grid 1024, 8 rows/CTA)
__global__ void __launch_bounds__(256) norm_k(const float* __restrict__ in1,
                                              const float* __restrict__ in2) {
    int row_g = blockIdx.x * 8 + (threadIdx.x >> 5);   // 0..8191
    int lane = threadIdx.x & 31;
    const float* src = (row_g < UU) ? in1 : in2;
    int row = row_g & (UU - 1);
    const float4* p = (const float4*)(src + (size_t)row * PP) + lane;

    float4 v0 = p[0],   v1 = p[32],  v2 = p[64],  v3 = p[96];
    float4 v4 = p[128], v5 = p[160], v6 = p[192], v7 = p[224];
    float s0 = v0.x * v0.x + v0.y * v0.y + v0.z * v0.z + v0.w * v0.w
             + v1.x * v1.x + v1.y * v1.y + v1.z * v1.z + v1.w * v1.w;
    float s1 = v2.x * v2.x + v2.y * v2.y + v2.z * v2.z + v2.w * v2.w
             + v3.x * v3.x + v3.y * v3.y + v3.z * v3.z + v3.w * v3.w;
    float s2 = v4.x * v4.x + v4.y * v4.y + v4.z * v4.z + v4.w * v4.w
             + v5.x * v5.x + v5.y * v5.y + v5.z * v5.z + v5.w * v5.w;
    float s3 = v6.x * v6.x + v6.y * v6.y + v6.z * v6.z + v6.w * v6.w
             + v7.x * v7.x + v7.y * v7.y + v7.z * v7.z + v7.w * v7.w;
    float ss = (s0 + s1) + (s2 + s3);
    #pragma unroll
    for (int o = 16; o > 0; o >>= 1) ss += __shfl_xor_sync(0xffffffffu, ss, o);
    if (lane == 0)
        g_inv[row_g] = 1.0f / fmaxf(sqrtf(ss), 1e-8f);
}

// fused scale + e4m3 convert + transpose (64x64 tiles) + partial column sums
__global__ void __launch_bounds__(256) conv_k(const float* __restrict__ in1,
                                              const float* __restrict__ in2) {
    int mat = blockIdx.z;
    const float* src = mat ? in2 : in1;
    uint8_t* dst = mat ? g_b2T : g_b1T;
    int c0 = blockIdx.x * 64, k0 = blockIdx.y * 64;
    __shared__ float s[64][65];
    int tid = threadIdx.x;
    #pragma unroll
    for (int r = 0; r < 4; r++) {
        int li = r * 256 + tid;
        int k = li >> 4, c4 = (li & 15) << 2;
        float4 v = *(const float4*)&src[(size_t)(k0 + k) * PP + c0 + c4];
        float inv = g_inv[mat * UU + k0 + k];
        s[c4 + 0][k] = v.x * inv; s[c4 + 1][k] = v.y * inv;
        s[c4 + 2][k] = v.z * inv; s[c4 + 3][k] = v.w * inv;
    }
    __syncthreads();
    int c = tid >> 2, kg = (tid & 3) << 4;
    uint32_t pk[4];
    #pragma unroll
    for (int t = 0; t < 4; t++)
        pk[t] = fp8x4(s[c][kg + 4 * t], s[c][kg + 4 * t + 1],
                      s[c][kg + 4 * t + 2], s[c][kg + 4 * t + 3]);
    *(uint4*)&dst[(size_t)(c0 + c) * UU + k0 + kg] = make_uint4(pk[0], pk[1], pk[2], pk[3]);
    float cs = 0.f;
    #pragma unroll
    for (int i = 0; i < 16; i++) cs += s[c][kg + i];
    cs += __shfl_xor_sync(0xffffffffu, cs, 1);
    cs += __shfl_xor_sync(0xffffffffu, cs, 2);
    if ((tid & 3) == 0) atomicAdd(&g_S[mat * PP + c0 + c], cs);
}

// FP8 Gram: grid 288 = 2 grams x 36 pairs x 4 K-quarters.
// 128 threads / 4 warps, 64x64 warp tiles (2x2); 96KB smem -> 2 CTAs/SM.
// Diagonal pairs (pt==qt) load only the A tile and alias B to it.
__global__ void __launch_bounds__(128, 2) gram_k() {
    extern __shared__ char dyn[];
    int b = blockIdx.x;
    int g = (b >= 144); int r0_ = b - g * 144;
    int q = r0_ / NPAIR; int pair = r0_ - q * NPAIR;
    int pt = 0, rem = pair;
    while (rem >= NTILE - pt) { rem -= NTILE - pt; pt++; }
    int qt = pt + rem;
    bool diag = (rem == 0);
    uint32_t bo = diag ? 0u : SUB_BYTES;   // B buffer offset within stage

    const uint8_t* src = g ? g_b2T : g_b1T;
    const uint4* PA = (const uint4*)src + (size_t)(pt * 128) * 256 + q * 64;
    const uint4* PB = (const uint4*)src + (size_t)(qt * 128) * 256 + q * 64;

    int tid = threadIdx.x;
    uint32_t sbase = (smem_u32(dyn) + 127u) & ~127u;

    int m0 = tid >> 3, c = tid & 7;
    int gbase = m0 * 256 + c;
    uint32_t sob = (uint32_t)(m0 * 128 + ((c ^ (m0 & 7)) << 4));

    int wid = tid >> 5, lane = tid & 31;
    int wm = wid >> 1, wn = wid & 1;
    int m_base = wm * 64, n_base = wn * 64;
    int lrow = lane & 15, lcol = lane >> 4;
    uint32_t offA[4], swA[4], offB[4], swB[4];
    #pragma unroll
    for (int t = 0; t < 4; t++) {
        int rwa = m_base + t * 16 + lrow;
        offA[t] = (uint32_t)(rwa * 128); swA[t] = (uint32_t)(rwa & 7);
        int rwb = n_base + t * 16 + lrow;
        offB[t] = (uint32_t)(rwb * 128); swB[t] = (uint32_t)(rwb & 7);
    }

    float acc[4][8][4];
    #pragma unroll
    for (int i = 0; i < 4; i++)
        #pragma unroll
        for (int j = 0; j < 8; j++)
            #pragma unroll
            for (int k = 0; k < 4; k++) acc[i][j][k] = 0.f;

    #pragma unroll
    for (int st = 0; st < 2; st++) {
        uint32_t sA = sbase + (uint32_t)(st * STAGE_BYTES);
        uint32_t sB = sA + SUB_BYTES;
        int k4 = st * 8;
        #pragma unroll
        for (int r = 0; r < 8; r++) {
            cp_async16(sA + sob + r * 2048, PA + gbase + r * 4096 + k4);
            if (!diag) cp_async16(sB + sob + r * 2048, PB + gbase + r * 4096 + k4);
        }
        cp_commit();
    }

    for (int ch = 0; ch < NCHUNK; ch++) {
        if (ch < NCHUNK - 1) asm volatile("cp.async.wait_group 1;" ::: "memory");
        else                 asm volatile("cp.async.wait_group 0;" ::: "memory");
        __syncthreads();
        if (ch + 2 < NCHUNK) {
            int st = (ch + 2) % NST;
            uint32_t sA = sbase + (uint32_t)(st * STAGE_BYTES);
            uint32_t sB = sA + SUB_BYTES;
            int k4 = (ch + 2) * 8;
            #pragma unroll
            for (int r = 0; r < 8; r++) {
                cp_async16(sA + sob + r * 2048, PA + gbase + r * 4096 + k4);
                if (!diag) cp_async16(sB + sob + r * 2048, PB + gbase + r * 4096 + k4);
            }
            cp_commit();
        }
        uint32_t sA = sbase + (uint32_t)((ch % NST) * STAGE_BYTES);
        uint32_t sB = sA + bo;   // diag: alias B reads to the A buffer
        #pragma unroll
        for (int kk = 0; kk < 4; kk++) {
            uint32_t cbase = (uint32_t)(kk * 2 + lcol);
            uint32_t bf[4][4];
            #pragma unroll
            for (int nt2 = 0; nt2 < 4; nt2++)
                ldsm_x4(bf[nt2][0], bf[nt2][1], bf[nt2][2], bf[nt2][3],
                        sB + offB[nt2] + (((cbase ^ swB[nt2]) & 7u) << 4));
            #pragma unroll
            for (int mt = 0; mt < 4; mt++) {
                uint32_t a0, a1, a2, a3;
                ldsm_x4(a0, a1, a2, a3,
                        sA + offA[mt] + (((cbase ^ swA[mt]) & 7u) << 4));
                #pragma unroll
                for (int nt2 = 0; nt2 < 4; nt2++) {
                    mma16832(acc[mt][2 * nt2 + 0], a0, a1, a2, a3, bf[nt2][0], bf[nt2][2]);
                    mma16832(acc[mt][2 * nt2 + 1], a0, a1, a2, a3, bf[nt2][1], bf[nt2][3]);
                }
            }
        }
    }

    // epilogue: direct per-warp bf16 pack
    int er = lane >> 2, ec = (lane & 3) << 1;
    uint32_t* out = g_Gb + (size_t)((g * 4 + q) * NPAIR + pair) * 8192;
    #pragma unroll
    for (int mt = 0; mt < 4; mt++)
        #pragma unroll
        for (int nt = 0; nt < 8; nt++) {
            int row = m_base + mt * 16 + er;
            int col = n_base + nt * 8 + ec;
            __nv_bfloat162 q0 = __floats2bfloat162_rn(acc[mt][nt][0], acc[mt][nt][1]);
            __nv_bfloat162 q1 = __floats2bfloat162_rn(acc[mt][nt][2], acc[mt][nt][3]);
            out[(row * 128 + col) >> 1]       = *(uint32_t*)&q0;
            out[((row + 8) * 128 + col) >> 1] = *(uint32_t*)&q1;
        }
}

// cross-dot (R14 config: grid 288, 8 parts/pair): batch 8 loads, sum quarters,
// dot, last-block finalize + reset.
__global__ void __launch_bounds__(256) dot_k(float* __restrict__ out) {
    int pair = blockIdx.x >> 3;
    int part = blockIdx.x & 7;
    int pt = 0, rem = pair;
    while (rem >= NTILE - pt) { rem -= NTILE - pt; pt++; }
    float w = (rem == 0) ? 1.0f : 2.0f;

    int tid = threadIdx.x;
    int idx = part * 256 + tid;   // uint4 index within tile (2048 total)

    uint4 ra[4], rb[4];
    #pragma unroll
    for (int qq = 0; qq < 4; qq++)
        ra[qq] = ((const uint4*)(g_Gb + (size_t)(qq * NPAIR + pair) * 8192))[idx];
    #pragma unroll
    for (int qq = 0; qq < 4; qq++)
        rb[qq] = ((const uint4*)(g_Gb + (size_t)((4 + qq) * NPAIR + pair) * 8192))[idx];

    float g1[8], g2[8];
    #pragma unroll
    for (int i = 0; i < 8; i++) { g1[i] = 0.f; g2[i] = 0.f; }
    #pragma unroll
    for (int qq = 0; qq < 4; qq++) {
        uint32_t wa[4] = {ra[qq].x, ra[qq].y, ra[qq].z, ra[qq].w};
        uint32_t wc[4] = {rb[qq].x, rb[qq].y, rb[qq].z, rb[qq].w};
        #pragma unroll
        for (int i = 0; i < 4; i++) {
            float2 fa = __bfloat1622float2(*(__nv_bfloat162*)&wa[i]);
            float2 fc = __bfloat1622float2(*(__nv_bfloat162*)&wc[i]);
            g1[2 * i] += fa.x; g1[2 * i + 1] += fa.y;
            g2[2 * i] += fc.x; g2[2 * i + 1] += fc.y;
        }
    }
    float s = 0.f;
    #pragma unroll
    for (int i = 0; i < 8; i++) s += g1[i] * g2[i];

    #pragma unroll
    for (int o = 16; o > 0; o >>= 1) s += __shfl_xor_sync(0xffffffffu, s, o);
    __shared__ float ws[8];
    if ((tid & 31) == 0) ws[tid >> 5] = s;
    __syncthreads();
    __shared__ int is_last;
    if (tid == 0) {
        float t = ws[0] + ws[1] + ws[2] + ws[3] + ws[4] + ws[5] + ws[6] + ws[7];
        atomicAdd(&g_part[pair], w * t);
        __threadfence();
        is_last = (atomicAdd(&g_done, 1u) == (unsigned)(gridDim.x - 1));
        if (is_last) __threadfence();
    }
    __syncthreads();
    if (is_last) {
        float sd = 0.f;
        #pragma unroll
        for (int r = 0; r < 4; r++) {
            int c = tid + r * 256;
            sd += g_S[c] * g_S[PP + c];
        }
        float cp = (tid < NPAIR) ? g_part[tid] : 0.0f;
        #pragma unroll
        for (int o = 16; o > 0; o >>= 1) {
            sd += __shfl_xor_sync(0xffffffffu, sd, o);
            cp += __shfl_xor_sync(0xffffffffu, cp, o);
        }
        __shared__ float wc2[8];
        if ((tid & 31) == 0) { ws[tid >> 5] = sd; wc2[tid >> 5] = cp; }
        __syncthreads();
        if (tid == 0) {
            float dot = ws[0] + ws[1] + ws[2] + ws[3] + ws[4] + ws[5] + ws[6] + ws[7];
            float cr  = wc2[0] + wc2[1] + wc2[2] + wc2[3] + wc2[4] + wc2[5] + wc2[6] + wc2[7];
            out[0] = (float)(16777216.0 - 2.0 * (double)dot + (double)cr);
        }
        __syncthreads();
        #pragma unroll
        for (int r = 0; r < 8; r++) g_S[tid + r * 256] = 0.0f;
        if (tid < NPAIR) g_part[tid] = 0.0f;
        if (tid == 0) g_done = 0u;
    }
}

// ============================================================================
extern "C" void kernel_launch(void* const* d_in, const int* in_sizes, int n_in,
                              void* d_out, int out_size) {
    const float* in1 = (const float*)d_in[0];
    const float* in2 = (const float*)d_in[1];
    float* out = (float*)d_out;

    cudaFuncSetAttribute(gram_k, cudaFuncAttributeMaxDynamicSharedMemorySize, GRAM_SMEM);

    norm_k<<<1024, 256>>>(in1, in2);
    conv_k<<<dim3(PP / 64, UU / 64, 2), 256>>>(in1, in2);
    gram_k<<<288, 128, GRAM_SMEM>>>();
    dot_k<<<NPAIR * 8, 256>>>(out);
}